// round 1
// baseline (speedup 1.0000x reference)
#include <cuda_runtime.h>
#include <cstdint>

#define N_USERS 100000
#define N_ITEMS 100000
#define DIM     128
#define NUM_R   4
#define N_EDGES 1000000

// ---------------- device scratch (static globals; no allocation) ----------------
__device__ float g_U[(size_t)N_USERS * DIM];
__device__ float g_I[(size_t)N_ITEMS * DIM];
__device__ float g_AGG[(size_t)N_USERS * DIM];   // N_USERS == N_ITEMS, shared scratch
__device__ float g_degU[NUM_R * N_USERS];
__device__ float g_degI[NUM_R * N_ITEMS];

// ---------------- degree computation (all relations at once) ----------------
__global__ void deg_kernel(const int* __restrict__ rows, const int* __restrict__ cols,
                           const float* __restrict__ vals)
{
    int idx = blockIdx.x * blockDim.x + threadIdx.x;
    const int total = NUM_R * N_EDGES;
    if (idx >= total) return;
    int r = idx / N_EDGES;
    float v = vals[idx];
    atomicAdd(&g_degU[r * N_USERS + rows[idx]], v);
    atomicAdd(&g_degI[r * N_ITEMS + cols[idx]], v);
}

// ---------------- SpMM: g_AGG[dst] += feats[src] * va  (warp per edge) ----------------
__global__ void spmm_kernel(const float* __restrict__ feats,
                            const int* __restrict__ src, const int* __restrict__ dst,
                            const float* __restrict__ va)
{
    int tid  = blockIdx.x * blockDim.x + threadIdx.x;
    int e    = tid >> 5;
    int lane = tid & 31;
    if (e >= N_EDGES) return;
    int   s = __ldg(src + e);
    int   d = __ldg(dst + e);
    float v = __ldg(va + e);
    float4 x = reinterpret_cast<const float4*>(feats + (size_t)s * DIM)[lane];
    x.x *= v; x.y *= v; x.z *= v; x.w *= v;
    float* p = g_AGG + (size_t)d * DIM + lane * 4;
    asm volatile("red.global.add.v4.f32 [%0], {%1,%2,%3,%4};"
                 :: "l"(p), "f"(x.x), "f"(x.y), "f"(x.z), "f"(x.w) : "memory");
}

// ---------------- fused update GEMM (in place, row-disjoint):
//   X[m,:] = X[m,:] @ Wp + (g_AGG[m,:] * 1/(deg[m]+1)) @ Ws
// Viewed as C[M,128] = A[M,256] @ B[256,128] with A = [X, inv*AGG], B = [Wp; Ws].
// BM=128, BN=128, BK=16, 256 threads, 8x8 register tile per thread.
__global__ __launch_bounds__(256)
void update_kernel(float* __restrict__ X, const float* __restrict__ deg,
                   const float* __restrict__ Wp, const float* __restrict__ Ws, int M)
{
    __shared__ float As[16][132];   // [k][m], padded
    __shared__ float Bs[16][128];   // [k][n]

    const int tid = threadIdx.x;
    const int tx  = tid & 15;       // output col group
    const int ty  = tid >> 4;       // output row group
    const int bm  = blockIdx.x * 128;

    // A-tile cooperative-load mapping: 2 threads per row, 8 k each
    const int lr = tid >> 1;            // 0..127
    const int lk = (tid & 1) * 8;       // 0 or 8
    const int arow  = bm + lr;
    const bool rowok = arow < M;
    const float invr = rowok ? 1.0f / (deg[arow] + 1.0f) : 0.0f;
    const float* Xrow = X     + (size_t)(rowok ? arow : 0) * DIM;
    const float* Grow = g_AGG + (size_t)(rowok ? arow : 0) * DIM;

    // B-tile cooperative-load mapping
    const int bk = tid >> 4;            // 0..15
    const int bn = (tid & 15) * 8;      // 0..120

    float acc[8][8];
#pragma unroll
    for (int i = 0; i < 8; ++i)
#pragma unroll
        for (int j = 0; j < 8; ++j) acc[i][j] = 0.0f;

#pragma unroll 1
    for (int t = 0; t < 16; ++t) {
        const int k0 = t * 16;
        // ---- load A tile ----
        float4 a0 = make_float4(0.f, 0.f, 0.f, 0.f), a1 = a0;
        if (rowok) {
            const float* s = (t < 8) ? (Xrow + k0 + lk) : (Grow + (k0 - 128) + lk);
            a0 = *reinterpret_cast<const float4*>(s);
            a1 = *reinterpret_cast<const float4*>(s + 4);
            if (t >= 8) {
                a0.x *= invr; a0.y *= invr; a0.z *= invr; a0.w *= invr;
                a1.x *= invr; a1.y *= invr; a1.z *= invr; a1.w *= invr;
            }
        }
        As[lk + 0][lr] = a0.x; As[lk + 1][lr] = a0.y;
        As[lk + 2][lr] = a0.z; As[lk + 3][lr] = a0.w;
        As[lk + 4][lr] = a1.x; As[lk + 5][lr] = a1.y;
        As[lk + 6][lr] = a1.z; As[lk + 7][lr] = a1.w;

        // ---- load B tile ----
        const float* bsrc = (t < 8) ? (Wp + (size_t)(k0 + bk) * DIM + bn)
                                    : (Ws + (size_t)(k0 - 128 + bk) * DIM + bn);
        float4 b0 = *reinterpret_cast<const float4*>(bsrc);
        float4 b1 = *reinterpret_cast<const float4*>(bsrc + 4);
        *reinterpret_cast<float4*>(&Bs[bk][bn])     = b0;
        *reinterpret_cast<float4*>(&Bs[bk][bn + 4]) = b1;

        __syncthreads();

#pragma unroll
        for (int k = 0; k < 16; ++k) {
            float4 av0 = *reinterpret_cast<const float4*>(&As[k][ty * 8]);
            float4 av1 = *reinterpret_cast<const float4*>(&As[k][ty * 8 + 4]);
            float4 bv0 = *reinterpret_cast<const float4*>(&Bs[k][tx * 8]);
            float4 bv1 = *reinterpret_cast<const float4*>(&Bs[k][tx * 8 + 4]);
            float a[8] = {av0.x, av0.y, av0.z, av0.w, av1.x, av1.y, av1.z, av1.w};
            float b[8] = {bv0.x, bv0.y, bv0.z, bv0.w, bv1.x, bv1.y, bv1.z, bv1.w};
#pragma unroll
            for (int i = 0; i < 8; ++i)
#pragma unroll
                for (int j = 0; j < 8; ++j)
                    acc[i][j] = fmaf(a[i], b[j], acc[i][j]);
        }
        __syncthreads();
    }

    // ---- write back (in place; all global reads of this block's rows are done) ----
#pragma unroll
    for (int i = 0; i < 8; ++i) {
        int row = bm + ty * 8 + i;
        if (row < M) {
            float4 o0 = make_float4(acc[i][0], acc[i][1], acc[i][2], acc[i][3]);
            float4 o1 = make_float4(acc[i][4], acc[i][5], acc[i][6], acc[i][7]);
            float* op = X + (size_t)row * DIM + tx * 8;
            *reinterpret_cast<float4*>(op)     = o0;
            *reinterpret_cast<float4*>(op + 4) = o1;
        }
    }
}

// ---------------- final leaky-relu + write out [U ; I] ----------------
__global__ void finalize_kernel(float* __restrict__ out)
{
    const size_t half4  = (size_t)N_USERS * DIM / 4;   // 3.2M float4
    const size_t total4 = 2 * half4;
    size_t idx = (size_t)blockIdx.x * blockDim.x + threadIdx.x;
    if (idx >= total4) return;
    float4 v = (idx < half4) ? reinterpret_cast<const float4*>(g_U)[idx]
                             : reinterpret_cast<const float4*>(g_I)[idx - half4];
    v.x = v.x > 0.f ? v.x : 0.01f * v.x;
    v.y = v.y > 0.f ? v.y : 0.01f * v.y;
    v.z = v.z > 0.f ? v.z : 0.01f * v.z;
    v.w = v.w > 0.f ? v.w : 0.01f * v.w;
    reinterpret_cast<float4*>(out)[idx] = v;
}

// ---------------- launch ----------------
extern "C" void kernel_launch(void* const* d_in, const int* in_sizes, int n_in,
                              void* d_out, int out_size)
{
    const float* u_emb = (const float*)d_in[0];
    const float* i_emb = (const float*)d_in[1];
    const float* Wp    = (const float*)d_in[2];
    const float* Ws    = (const float*)d_in[3];
    const float* vals  = (const float*)d_in[4];
    const int*   rows  = (const int*)d_in[5];
    const int*   cols  = (const int*)d_in[6];
    float*       out   = (float*)d_out;

    void *pU, *pI, *pAGG, *pDU, *pDI;
    cudaGetSymbolAddress(&pU,  g_U);
    cudaGetSymbolAddress(&pI,  g_I);
    cudaGetSymbolAddress(&pAGG, g_AGG);
    cudaGetSymbolAddress(&pDU, g_degU);
    cudaGetSymbolAddress(&pDI, g_degI);

    const size_t embBytes = (size_t)N_USERS * DIM * sizeof(float);
    cudaMemcpyAsync(pU, u_emb, embBytes, cudaMemcpyDeviceToDevice, 0);
    cudaMemcpyAsync(pI, i_emb, embBytes, cudaMemcpyDeviceToDevice, 0);
    cudaMemsetAsync(pDU, 0, sizeof(float) * NUM_R * N_USERS, 0);
    cudaMemsetAsync(pDI, 0, sizeof(float) * NUM_R * N_ITEMS, 0);

    deg_kernel<<<(NUM_R * N_EDGES + 255) / 256, 256>>>(rows, cols, vals);

    const int spmm_blocks   = (N_EDGES * 32 + 255) / 256;        // 125000
    const int update_blocks = (N_USERS + 127) / 128;             // 782

    for (int r = 0; r < NUM_R; ++r) {
        const int*   ro  = rows + (size_t)r * N_EDGES;
        const int*   co  = cols + (size_t)r * N_EDGES;
        const float* va  = vals + (size_t)r * N_EDGES;
        const float* Wsr = Ws + (size_t)r * DIM * DIM;

        // ---- u update: agg_u = A @ I  (src = cols, dst = rows) ----
        cudaMemsetAsync(pAGG, 0, embBytes, 0);
        spmm_kernel<<<spmm_blocks, 256>>>((const float*)pI, co, ro, va);
        update_kernel<<<update_blocks, 256>>>((float*)pU,
                                              (const float*)pDU + (size_t)r * N_USERS,
                                              Wp, Wsr, N_USERS);

        // ---- i update: agg_i = A^T @ U (src = rows, dst = cols), uses updated U ----
        cudaMemsetAsync(pAGG, 0, embBytes, 0);
        spmm_kernel<<<spmm_blocks, 256>>>((const float*)pU, ro, co, va);
        update_kernel<<<update_blocks, 256>>>((float*)pI,
                                              (const float*)pDI + (size_t)r * N_ITEMS,
                                              Wp, Wsr, N_ITEMS);
    }

    const size_t total4 = 2 * ((size_t)N_USERS * DIM / 4);
    finalize_kernel<<<(unsigned)((total4 + 255) / 256), 256>>>(out);
}

// round 5
// speedup vs baseline: 1.2690x; 1.2690x over previous
#include <cuda_runtime.h>
#include <cuda_bf16.h>
#include <mma.h>
#include <cstdint>
#include <cstring>

using namespace nvcuda;

#define N_USERS 100000
#define N_ITEMS 100000
#define DIM     128
#define NUM_R   4
#define N_EDGES 1000000

// ---------------- device scratch (static globals; no allocation) ----------------
__device__ float g_U[(size_t)N_USERS * DIM];
__device__ float g_I[(size_t)N_ITEMS * DIM];
__device__ float g_AGG[(size_t)N_USERS * DIM];
__device__ float g_degU[NUM_R * N_USERS];
__device__ float g_degI[NUM_R * N_ITEMS];
// prepared weights: 5 weights (Wp, Ws[0..3]) x (hi,lo) x [n=128][k=128] bf16, packed row-major
__device__ __nv_bfloat16 g_Wb[(size_t)5 * 2 * 16384];

// ---------------- degree computation ----------------
__global__ void deg_kernel(const int* __restrict__ rows, const int* __restrict__ cols,
                           const float* __restrict__ vals)
{
    int idx = blockIdx.x * blockDim.x + threadIdx.x;
    const int total = NUM_R * N_EDGES;
    if (idx >= total) return;
    int r = idx / N_EDGES;
    float v = vals[idx];
    atomicAdd(&g_degU[r * N_USERS + rows[idx]], v);
    atomicAdd(&g_degI[r * N_ITEMS + cols[idx]], v);
}

// ---------------- SpMM scatter ----------------
__global__ void spmm_kernel(const float* __restrict__ feats,
                            const int* __restrict__ src, const int* __restrict__ dst,
                            const float* __restrict__ va)
{
    int tid  = blockIdx.x * blockDim.x + threadIdx.x;
    int e    = tid >> 5;
    int lane = tid & 31;
    if (e >= N_EDGES) return;
    int   s = __ldg(src + e);
    int   d = __ldg(dst + e);
    float v = __ldg(va + e);
    float4 x = reinterpret_cast<const float4*>(feats + (size_t)s * DIM)[lane];
    x.x *= v; x.y *= v; x.z *= v; x.w *= v;
    float* p = g_AGG + (size_t)d * DIM + lane * 4;
    asm volatile("red.global.add.v4.f32 [%0], {%1,%2,%3,%4};"
                 :: "l"(p), "f"(x.x), "f"(x.y), "f"(x.z), "f"(x.w) : "memory");
}

// ---------------- weight prep: transpose + bf16 split ----------------
// B[n][k] = W[k][n]; hi/lo stored packed row-major [128][128] bf16.
__global__ __launch_bounds__(256) void wprep_kernel(const float* __restrict__ Wp,
                                                    const float* __restrict__ Ws)
{
    int w = blockIdx.x;  // 0 = Wp, 1..4 = Ws[r]
    const float* W = (w == 0) ? Wp : Ws + (size_t)(w - 1) * DIM * DIM;
    __nv_bfloat16* hi = g_Wb + (size_t)w * 2 * 16384;
    __nv_bfloat16* lo = hi + 16384;
    for (int e = threadIdx.x; e < DIM * DIM; e += blockDim.x) {
        int k = e >> 7, n = e & 127;
        float x = W[e];
        __nv_bfloat16 h = __float2bfloat16(x);
        __nv_bfloat16 l = __float2bfloat16(x - __bfloat162float(h));
        hi[n * DIM + k] = h;
        lo[n * DIM + k] = l;
    }
}

// ================= WMMA update GEMM =================
// X[tile,:] = X @ Wp + (inv*AGG) @ Ws, fp32 via bf16 split (hi*hi + hi*lo + lo*hi)
// Block: 256 threads (8 warps), tile M=128, N=128. Warp tile m32 x n64.
// smem: A hi/lo [128][136] bf16; B hi/lo [128][136] bf16; inv[128].

#define LDA       136              // smem leading dim in elements (bf16)
#define ASTRIDE_B (LDA * 2)        // 272 bytes
#define SM_INV    0
#define SM_AH     1024
#define SM_AL     (SM_AH + 128 * ASTRIDE_B)   // 35840
#define SM_BH     (SM_AL + 128 * ASTRIDE_B)   // 70656
#define SM_BL     (SM_BH + 128 * ASTRIDE_B)   // 105472
#define SM_BYTES  (SM_BL + 128 * ASTRIDE_B)   // 140288

typedef wmma::fragment<wmma::matrix_a, 16, 16, 16, __nv_bfloat16, wmma::row_major> FragA;
typedef wmma::fragment<wmma::matrix_b, 16, 16, 16, __nv_bfloat16, wmma::col_major> FragB;
typedef wmma::fragment<wmma::accumulator, 16, 16, 16, float> FragC;

// convert fp32 tile rows -> bf16 hi/lo smem [128][136]
__device__ __forceinline__ void cvt_tile(const float* __restrict__ src, int bm, int M,
                                         char* sm, const float* sInv, int tid, bool scale)
{
    char* hi = sm + SM_AH;
    char* lo = sm + SM_AL;
#pragma unroll 4
    for (int it = 0; it < 16; ++it) {
        int idx = it * 256 + tid;
        int r = idx >> 5, c4 = idx & 31;
        int rowg = bm + r;
        if (rowg >= M) rowg = M - 1;
        float4 v = *reinterpret_cast<const float4*>(src + (size_t)rowg * DIM + c4 * 4);
        if (scale) { float s = sInv[r]; v.x *= s; v.y *= s; v.z *= s; v.w *= s; }
        __nv_bfloat162 h01 = __floats2bfloat162_rn(v.x, v.y);
        __nv_bfloat162 h23 = __floats2bfloat162_rn(v.z, v.w);
        __nv_bfloat162 l01 = __floats2bfloat162_rn(v.x - __bfloat162float(h01.x),
                                                   v.y - __bfloat162float(h01.y));
        __nv_bfloat162 l23 = __floats2bfloat162_rn(v.z - __bfloat162float(h23.x),
                                                   v.w - __bfloat162float(h23.y));
        uint32_t off = (uint32_t)r * ASTRIDE_B + (uint32_t)c4 * 8;
        uint2 hv, lv;
        memcpy(&hv.x, &h01, 4); memcpy(&hv.y, &h23, 4);
        memcpy(&lv.x, &l01, 4); memcpy(&lv.y, &l23, 4);
        *reinterpret_cast<uint2*>(hi + off) = hv;
        *reinterpret_cast<uint2*>(lo + off) = lv;
    }
}

// copy packed [128][128] bf16 hi+lo weight -> smem [128][136]
// 128 bf16 per row = 256 bytes = 16 float4; 2048 float4 per matrix.
__device__ __forceinline__ void copy_B(const __nv_bfloat16* __restrict__ wpair,
                                       char* sm, int tid)
{
    const float4* shi = reinterpret_cast<const float4*>(wpair);
    const float4* slo = reinterpret_cast<const float4*>(wpair + 16384);
    char* dhi = sm + SM_BH;
    char* dlo = sm + SM_BL;
#pragma unroll
    for (int i = 0; i < 8; ++i) {
        int idx = i * 256 + tid;            // 0..2047
        int row = idx >> 4, c = idx & 15;   // 16 float4 per 128-bf16 row
        uint32_t off = (uint32_t)row * ASTRIDE_B + (uint32_t)c * 16;
        *reinterpret_cast<float4*>(dhi + off) = shi[idx];
        *reinterpret_cast<float4*>(dlo + off) = slo[idx];
    }
}

// one GEMM term: acc += A(m32 x 128) * B^T(n64 x 128), K=128
__device__ __forceinline__ void mma_term(const __nv_bfloat16* aStrip,
                                         const __nv_bfloat16* bStrip,
                                         FragC (&acc)[2][4])
{
#pragma unroll
    for (int ks = 0; ks < 8; ++ks) {
        FragA a[2];
        FragB b[4];
#pragma unroll
        for (int mi = 0; mi < 2; ++mi)
            wmma::load_matrix_sync(a[mi], aStrip + (size_t)(mi * 16) * LDA + ks * 16, LDA);
#pragma unroll
        for (int j = 0; j < 4; ++j)
            wmma::load_matrix_sync(b[j], bStrip + (size_t)(j * 16) * LDA + ks * 16, LDA);
#pragma unroll
        for (int mi = 0; mi < 2; ++mi)
#pragma unroll
            for (int j = 0; j < 4; ++j)
                wmma::mma_sync(acc[mi][j], a[mi], b[j], acc[mi][j]);
    }
}

__global__ __launch_bounds__(256, 1)
void update_mma_kernel(float* __restrict__ X, const float* __restrict__ deg,
                       const __nv_bfloat16* __restrict__ wp_pair,
                       const __nv_bfloat16* __restrict__ ws_pair, int M)
{
    extern __shared__ char sm[];
    const int tid  = threadIdx.x;
    const int wid  = tid >> 5;
    const int bm   = blockIdx.x * 128;
    const int mg   = wid & 3;   // row group (m32)
    const int ng   = wid >> 2;  // col group (n64)

    float* sInv = (float*)(sm + SM_INV);
    if (tid < 128) {
        int rowg = bm + tid;
        sInv[tid] = (rowg < M) ? 1.0f / (deg[rowg] + 1.0f) : 0.0f;
    }

    FragC acc[2][4];
#pragma unroll
    for (int mi = 0; mi < 2; ++mi)
#pragma unroll
        for (int j = 0; j < 4; ++j) wmma::fill_fragment(acc[mi][j], 0.0f);

    const __nv_bfloat16* aH = (const __nv_bfloat16*)(sm + SM_AH) + (size_t)mg * 32 * LDA;
    const __nv_bfloat16* aL = (const __nv_bfloat16*)(sm + SM_AL) + (size_t)mg * 32 * LDA;
    const __nv_bfloat16* bH = (const __nv_bfloat16*)(sm + SM_BH) + (size_t)ng * 64 * LDA;
    const __nv_bfloat16* bL = (const __nv_bfloat16*)(sm + SM_BL) + (size_t)ng * 64 * LDA;

    // ===== phase 0: A = X, B = Wp =====
    cvt_tile(X, bm, M, sm, sInv, tid, false);
    copy_B(wp_pair, sm, tid);
    __syncthreads();
    mma_term(aH, bH, acc);
    mma_term(aH, bL, acc);
    mma_term(aL, bH, acc);
    __syncthreads();

    // ===== phase 1: A = inv*AGG, B = Ws =====
    cvt_tile(g_AGG, bm, M, sm, sInv, tid, true);
    copy_B(ws_pair, sm, tid);
    __syncthreads();
    mma_term(aH, bH, acc);
    mma_term(aH, bL, acc);
    mma_term(aL, bH, acc);
    __syncthreads();

    // ===== epilogue: stage in smem, coalesced in-place write =====
    float* stag = (float*)(sm + SM_AH);  // 64KB staging (fits in A region)
#pragma unroll
    for (int mi = 0; mi < 2; ++mi)
#pragma unroll
        for (int j = 0; j < 4; ++j) {
            float* dst = stag + (size_t)(mg * 32 + mi * 16) * 128 + ng * 64 + j * 16;
            wmma::store_matrix_sync(dst, acc[mi][j], 128, wmma::mem_row_major);
        }
    __syncthreads();
#pragma unroll 4
    for (int it = 0; it < 16; ++it) {
        int idx = it * 256 + tid;
        int r = idx >> 5, c4 = idx & 31;
        int rowg = bm + r;
        if (rowg < M)
            *reinterpret_cast<float4*>(X + (size_t)rowg * DIM + c4 * 4) =
                *reinterpret_cast<const float4*>(&stag[(size_t)r * 128 + c4 * 4]);
    }
}

// ---------------- final leaky-relu + write out [U ; I] ----------------
__global__ void finalize_kernel(float* __restrict__ out)
{
    const size_t half4  = (size_t)N_USERS * DIM / 4;
    const size_t total4 = 2 * half4;
    size_t idx = (size_t)blockIdx.x * blockDim.x + threadIdx.x;
    if (idx >= total4) return;
    float4 v = (idx < half4) ? reinterpret_cast<const float4*>(g_U)[idx]
                             : reinterpret_cast<const float4*>(g_I)[idx - half4];
    v.x = v.x > 0.f ? v.x : 0.01f * v.x;
    v.y = v.y > 0.f ? v.y : 0.01f * v.y;
    v.z = v.z > 0.f ? v.z : 0.01f * v.z;
    v.w = v.w > 0.f ? v.w : 0.01f * v.w;
    reinterpret_cast<float4*>(out)[idx] = v;
}

// ---------------- launch ----------------
extern "C" void kernel_launch(void* const* d_in, const int* in_sizes, int n_in,
                              void* d_out, int out_size)
{
    const float* u_emb = (const float*)d_in[0];
    const float* i_emb = (const float*)d_in[1];
    const float* Wp    = (const float*)d_in[2];
    const float* Ws    = (const float*)d_in[3];
    const float* vals  = (const float*)d_in[4];
    const int*   rows  = (const int*)d_in[5];
    const int*   cols  = (const int*)d_in[6];
    float*       out   = (float*)d_out;

    void *pU, *pI, *pAGG, *pDU, *pDI, *pWb;
    cudaGetSymbolAddress(&pU,  g_U);
    cudaGetSymbolAddress(&pI,  g_I);
    cudaGetSymbolAddress(&pAGG, g_AGG);
    cudaGetSymbolAddress(&pDU, g_degU);
    cudaGetSymbolAddress(&pDI, g_degI);
    cudaGetSymbolAddress(&pWb, g_Wb);

    cudaFuncSetAttribute(update_mma_kernel, cudaFuncAttributeMaxDynamicSharedMemorySize, SM_BYTES);

    const size_t embBytes = (size_t)N_USERS * DIM * sizeof(float);
    cudaMemcpyAsync(pU, u_emb, embBytes, cudaMemcpyDeviceToDevice, 0);
    cudaMemcpyAsync(pI, i_emb, embBytes, cudaMemcpyDeviceToDevice, 0);
    cudaMemsetAsync(pDU, 0, sizeof(float) * NUM_R * N_USERS, 0);
    cudaMemsetAsync(pDI, 0, sizeof(float) * NUM_R * N_ITEMS, 0);

    wprep_kernel<<<5, 256>>>(Wp, Ws);
    deg_kernel<<<(NUM_R * N_EDGES + 255) / 256, 256>>>(rows, cols, vals);

    const int spmm_blocks   = (N_EDGES * 32 + 255) / 256;
    const int update_blocks = (N_USERS + 127) / 128;
    const __nv_bfloat16* wb = (const __nv_bfloat16*)pWb;

    for (int r = 0; r < NUM_R; ++r) {
        const int*   ro  = rows + (size_t)r * N_EDGES;
        const int*   co  = cols + (size_t)r * N_EDGES;
        const float* va  = vals + (size_t)r * N_EDGES;
        const __nv_bfloat16* wp_pair = wb;                                // Wp hi+lo
        const __nv_bfloat16* ws_pair = wb + (size_t)(1 + r) * 2 * 16384;  // Ws[r] hi+lo

        // ---- u update ----
        cudaMemsetAsync(pAGG, 0, embBytes, 0);
        spmm_kernel<<<spmm_blocks, 256>>>((const float*)pI, co, ro, va);
        update_mma_kernel<<<update_blocks, 256, SM_BYTES>>>(
            (float*)pU, (const float*)pDU + (size_t)r * N_USERS, wp_pair, ws_pair, N_USERS);

        // ---- i update (uses updated U) ----
        cudaMemsetAsync(pAGG, 0, embBytes, 0);
        spmm_kernel<<<spmm_blocks, 256>>>((const float*)pU, ro, co, va);
        update_mma_kernel<<<update_blocks, 256, SM_BYTES>>>(
            (float*)pI, (const float*)pDI + (size_t)r * N_ITEMS, wp_pair, ws_pair, N_ITEMS);
    }

    const size_t total4 = 2 * ((size_t)N_USERS * DIM / 4);
    finalize_kernel<<<(unsigned)((total4 + 255) / 256), 256>>>(out);
}

// round 6
// speedup vs baseline: 1.4653x; 1.1547x over previous
#include <cuda_runtime.h>
#include <cuda_bf16.h>
#include <mma.h>
#include <cstdint>
#include <cstring>

using namespace nvcuda;

#define N_USERS 100000
#define N_ITEMS 100000
#define DIM     128
#define NUM_R   4
#define N_EDGES 1000000

#define GRID_U  148
#define TM      64
#define NT      ((N_USERS + TM - 1) / TM)   // 1563

// ---------------- device scratch (static globals; no allocation) ----------------
__device__ float g_U[(size_t)N_USERS * DIM];
__device__ float g_I[(size_t)N_ITEMS * DIM];
__device__ float g_AGG[(size_t)N_USERS * DIM];   // zero-init; updates re-zero after use
__device__ float g_degU[NUM_R * N_USERS];
__device__ float g_degI[NUM_R * N_ITEMS];
// prepared weights: 5 weights (Wp, Ws[0..3]) x (hi,lo) x [n=128][k=128] bf16, packed row-major
__device__ __nv_bfloat16 g_Wb[(size_t)5 * 2 * 16384];

// ---------------- degree computation ----------------
__global__ void deg_kernel(const int* __restrict__ rows, const int* __restrict__ cols,
                           const float* __restrict__ vals)
{
    int idx = blockIdx.x * blockDim.x + threadIdx.x;
    const int total = NUM_R * N_EDGES;
    if (idx >= total) return;
    int r = idx / N_EDGES;
    float v = vals[idx];
    atomicAdd(&g_degU[r * N_USERS + rows[idx]], v);
    atomicAdd(&g_degI[r * N_ITEMS + cols[idx]], v);
}

// ---------------- SpMM scatter ----------------
__global__ void spmm_kernel(const float* __restrict__ feats,
                            const int* __restrict__ src, const int* __restrict__ dst,
                            const float* __restrict__ va)
{
    int tid  = blockIdx.x * blockDim.x + threadIdx.x;
    int e    = tid >> 5;
    int lane = tid & 31;
    if (e >= N_EDGES) return;
    int   s = __ldg(src + e);
    int   d = __ldg(dst + e);
    float v = __ldg(va + e);
    float4 x = reinterpret_cast<const float4*>(feats + (size_t)s * DIM)[lane];
    x.x *= v; x.y *= v; x.z *= v; x.w *= v;
    float* p = g_AGG + (size_t)d * DIM + lane * 4;
    asm volatile("red.global.add.v4.f32 [%0], {%1,%2,%3,%4};"
                 :: "l"(p), "f"(x.x), "f"(x.y), "f"(x.z), "f"(x.w) : "memory");
}

// ---------------- weight prep: transpose + bf16 split ----------------
__global__ __launch_bounds__(256) void wprep_kernel(const float* __restrict__ Wp,
                                                    const float* __restrict__ Ws)
{
    int w = blockIdx.x;  // 0 = Wp, 1..4 = Ws[r]
    const float* W = (w == 0) ? Wp : Ws + (size_t)(w - 1) * DIM * DIM;
    __nv_bfloat16* hi = g_Wb + (size_t)w * 2 * 16384;
    __nv_bfloat16* lo = hi + 16384;
    for (int e = threadIdx.x; e < DIM * DIM; e += blockDim.x) {
        int k = e >> 7, n = e & 127;
        float x = W[e];
        __nv_bfloat16 h = __float2bfloat16(x);
        __nv_bfloat16 l = __float2bfloat16(x - __bfloat162float(h));
        hi[n * DIM + k] = h;
        lo[n * DIM + k] = l;
    }
}

// ================= persistent WMMA update GEMM =================
// X[tile,:] = X @ Wp + (inv*AGG) @ Ws, fp32 via bf16 split (hi*hi + hi*lo + lo*hi)
// Persistent: 148 CTAs x 256 threads; B (4 matrices) loaded to smem once; M-tile 64.
// Pipeline: cp.async stage buffer prefetches AGG during phase-0 MMA and next X
// during phase-1 MMA. Epilogue stores direct to global and zeroes consumed AGG rows.

#define LDA       136              // smem leading dim in elements (bf16)
#define ASTRIDE_B (LDA * 2)        // 272 bytes
#define SM_INV    0
#define SM_STAGE  1024                        // 64x128 fp32 = 32768
#define SM_AH     (SM_STAGE + 32768)          // 33792
#define SM_AL     (SM_AH + TM * ASTRIDE_B)    // +17408 = 51200
#define SM_B      (SM_AL + TM * ASTRIDE_B)    // 68608 ; 4 x [128][136] bf16
#define BMAT      (128 * ASTRIDE_B)           // 34816
#define SM_BYTES  (SM_B + 4 * BMAT)           // 207872

typedef wmma::fragment<wmma::matrix_a, 16, 16, 16, __nv_bfloat16, wmma::row_major> FragA;
typedef wmma::fragment<wmma::matrix_b, 16, 16, 16, __nv_bfloat16, wmma::col_major> FragB;
typedef wmma::fragment<wmma::accumulator, 16, 16, 16, float> FragC;

__device__ __forceinline__ uint32_t smem_u32(const void* p) {
    uint32_t a;
    asm("{ .reg .u64 t; cvta.to.shared.u64 t, %1; cvt.u32.u64 %0, t; }" : "=r"(a) : "l"(p));
    return a;
}
__device__ __forceinline__ void cp_async16(uint32_t smem_dst, const void* gsrc) {
    asm volatile("cp.async.cg.shared.global [%0], [%1], 16;" :: "r"(smem_dst), "l"(gsrc));
}
#define CP_COMMIT() asm volatile("cp.async.commit_group;" ::: "memory")
#define CP_WAIT0()  asm volatile("cp.async.wait_group 0;" ::: "memory")

// prefetch one 64-row fp32 tile into stage (row-clamped), 8 x 16B per thread
__device__ __forceinline__ void stage_load(const float* __restrict__ src, int bm, int M,
                                           uint32_t stageAddr, int tid)
{
#pragma unroll
    for (int i = 0; i < 8; ++i) {
        int idx = i * 256 + tid;            // 0..2047
        int r = idx >> 5, c4 = idx & 31;
        int rowg = bm + r;
        if (rowg >= M) rowg = M - 1;
        cp_async16(stageAddr + (uint32_t)idx * 16, src + (size_t)rowg * DIM + c4 * 4);
    }
    CP_COMMIT();
}

// convert staged fp32 tile -> bf16 hi/lo smem [64][136]
__device__ __forceinline__ void cvt_stage(const char* __restrict__ stage, char* hi, char* lo,
                                          const float* sInv, int tid, bool scale)
{
#pragma unroll
    for (int it = 0; it < 8; ++it) {
        int idx = it * 256 + tid;
        int r = idx >> 5, c4 = idx & 31;
        float4 v = *reinterpret_cast<const float4*>(stage + (size_t)idx * 16);
        if (scale) { float s = sInv[r]; v.x *= s; v.y *= s; v.z *= s; v.w *= s; }
        __nv_bfloat162 h01 = __floats2bfloat162_rn(v.x, v.y);
        __nv_bfloat162 h23 = __floats2bfloat162_rn(v.z, v.w);
        __nv_bfloat162 l01 = __floats2bfloat162_rn(v.x - __bfloat162float(h01.x),
                                                   v.y - __bfloat162float(h01.y));
        __nv_bfloat162 l23 = __floats2bfloat162_rn(v.z - __bfloat162float(h23.x),
                                                   v.w - __bfloat162float(h23.y));
        uint32_t off = (uint32_t)r * ASTRIDE_B + (uint32_t)c4 * 8;
        uint2 hv, lv;
        memcpy(&hv.x, &h01, 4); memcpy(&hv.y, &h23, 4);
        memcpy(&lv.x, &l01, 4); memcpy(&lv.y, &l23, 4);
        *reinterpret_cast<uint2*>(hi + off) = hv;
        *reinterpret_cast<uint2*>(lo + off) = lv;
    }
}

// one GEMM term: acc += A(m32 x 128) * B^T(n32 x 128), K=128
__device__ __forceinline__ void mma_term(const __nv_bfloat16* aStrip,
                                         const __nv_bfloat16* bStrip,
                                         FragC (&acc)[2][2])
{
#pragma unroll
    for (int ks = 0; ks < 8; ++ks) {
        FragA a[2];
        FragB b[2];
#pragma unroll
        for (int mi = 0; mi < 2; ++mi)
            wmma::load_matrix_sync(a[mi], aStrip + (size_t)(mi * 16) * LDA + ks * 16, LDA);
#pragma unroll
        for (int j = 0; j < 2; ++j)
            wmma::load_matrix_sync(b[j], bStrip + (size_t)(j * 16) * LDA + ks * 16, LDA);
#pragma unroll
        for (int mi = 0; mi < 2; ++mi)
#pragma unroll
            for (int j = 0; j < 2; ++j)
                wmma::mma_sync(acc[mi][j], a[mi], b[j], acc[mi][j]);
    }
}

__global__ __launch_bounds__(256, 1)
void update_mma_kernel(float* __restrict__ X, const float* __restrict__ deg,
                       const __nv_bfloat16* __restrict__ wp_pair,
                       const __nv_bfloat16* __restrict__ ws_pair, int M)
{
    extern __shared__ char sm[];
    const uint32_t sb = smem_u32(sm);
    const int tid = threadIdx.x;
    const int wid = tid >> 5;
    const int mg  = wid & 1;    // m32 group
    const int ng  = wid >> 1;   // n32 group

    // ---- load all 4 B matrices to smem once ----
    {
        const float4* srcs[4] = {
            reinterpret_cast<const float4*>(wp_pair),
            reinterpret_cast<const float4*>(wp_pair + 16384),
            reinterpret_cast<const float4*>(ws_pair),
            reinterpret_cast<const float4*>(ws_pair + 16384)};
#pragma unroll
        for (int w = 0; w < 4; ++w) {
            char* dst = sm + SM_B + w * BMAT;
#pragma unroll
            for (int i = 0; i < 8; ++i) {
                int idx = i * 256 + tid;            // 0..2047
                int row = idx >> 4, c = idx & 15;   // 16 float4 per 128-bf16 row
                *reinterpret_cast<float4*>(dst + (uint32_t)row * ASTRIDE_B + c * 16) = srcs[w][idx];
            }
        }
    }

    float* sInv = (float*)(sm + SM_INV);
    const uint32_t stageAddr = sb + SM_STAGE;
    char* stage = sm + SM_STAGE;
    char* aHbuf = sm + SM_AH;
    char* aLbuf = sm + SM_AL;

    const __nv_bfloat16* aH = (const __nv_bfloat16*)aHbuf + (size_t)mg * 32 * LDA;
    const __nv_bfloat16* aL = (const __nv_bfloat16*)aLbuf + (size_t)mg * 32 * LDA;
    const __nv_bfloat16* bPH = (const __nv_bfloat16*)(sm + SM_B + 0 * BMAT) + (size_t)ng * 32 * LDA;
    const __nv_bfloat16* bPL = (const __nv_bfloat16*)(sm + SM_B + 1 * BMAT) + (size_t)ng * 32 * LDA;
    const __nv_bfloat16* bSH = (const __nv_bfloat16*)(sm + SM_B + 2 * BMAT) + (size_t)ng * 32 * LDA;
    const __nv_bfloat16* bSL = (const __nv_bfloat16*)(sm + SM_B + 3 * BMAT) + (size_t)ng * 32 * LDA;

    // ---- prologue: prefetch first X tile ----
    stage_load(X, (int)blockIdx.x * TM, M, stageAddr, tid);

    for (int t = blockIdx.x; t < NT; t += GRID_U) {
        const int bm = t * TM;
        if (tid < TM) {
            int rowg = bm + tid;
            sInv[tid] = (rowg < M) ? 1.0f / (deg[rowg] + 1.0f) : 0.0f;
        }

        FragC acc[2][2];
#pragma unroll
        for (int mi = 0; mi < 2; ++mi)
#pragma unroll
            for (int j = 0; j < 2; ++j) wmma::fill_fragment(acc[mi][j], 0.0f);

        // ===== phase 0: A = X, B = Wp =====
        CP_WAIT0();
        __syncthreads();                 // X tile landed; prev-iter MMA/epilogue done
        cvt_stage(stage, aHbuf, aLbuf, sInv, tid, false);
        __syncthreads();
        stage_load(g_AGG, bm, M, stageAddr, tid);   // prefetch AGG during MMA
        mma_term(aH, bPH, acc);
        mma_term(aH, bPL, acc);
        mma_term(aL, bPH, acc);

        // ===== phase 1: A = inv*AGG, B = Ws =====
        CP_WAIT0();
        __syncthreads();                 // AGG landed; all warps done with phase-0 A
        cvt_stage(stage, aHbuf, aLbuf, sInv, tid, true);
        __syncthreads();
        if (t + GRID_U < NT)             // prefetch next X tile during MMA/epilogue
            stage_load(X, (t + GRID_U) * TM, M, stageAddr, tid);
        mma_term(aH, bSH, acc);
        mma_term(aH, bSL, acc);
        mma_term(aL, bSH, acc);

        // ===== epilogue: direct global store + zero consumed AGG rows =====
#pragma unroll
        for (int mi = 0; mi < 2; ++mi) {
            int row0 = bm + mg * 32 + mi * 16;
            if (row0 < M) {              // M % 16 == 0: whole-fragment granularity
#pragma unroll
                for (int j = 0; j < 2; ++j)
                    wmma::store_matrix_sync(X + (size_t)row0 * DIM + ng * 32 + j * 16,
                                            acc[mi][j], DIM, wmma::mem_row_major);
            }
        }
        float4 z = make_float4(0.f, 0.f, 0.f, 0.f);
#pragma unroll
        for (int i = 0; i < 8; ++i) {
            int idx = i * 256 + tid;
            int r = idx >> 5, c4 = idx & 31;
            int rowg = bm + r;
            if (rowg < M)
                *reinterpret_cast<float4*>(g_AGG + (size_t)rowg * DIM + c4 * 4) = z;
        }
    }
}

// ---------------- final leaky-relu + write out [U ; I] ----------------
__global__ void finalize_kernel(float* __restrict__ out)
{
    const size_t half4  = (size_t)N_USERS * DIM / 4;
    const size_t total4 = 2 * half4;
    size_t idx = (size_t)blockIdx.x * blockDim.x + threadIdx.x;
    if (idx >= total4) return;
    float4 v = (idx < half4) ? reinterpret_cast<const float4*>(g_U)[idx]
                             : reinterpret_cast<const float4*>(g_I)[idx - half4];
    v.x = v.x > 0.f ? v.x : 0.01f * v.x;
    v.y = v.y > 0.f ? v.y : 0.01f * v.y;
    v.z = v.z > 0.f ? v.z : 0.01f * v.z;
    v.w = v.w > 0.f ? v.w : 0.01f * v.w;
    reinterpret_cast<float4*>(out)[idx] = v;
}

// ---------------- launch ----------------
extern "C" void kernel_launch(void* const* d_in, const int* in_sizes, int n_in,
                              void* d_out, int out_size)
{
    const float* u_emb = (const float*)d_in[0];
    const float* i_emb = (const float*)d_in[1];
    const float* Wp    = (const float*)d_in[2];
    const float* Ws    = (const float*)d_in[3];
    const float* vals  = (const float*)d_in[4];
    const int*   rows  = (const int*)d_in[5];
    const int*   cols  = (const int*)d_in[6];
    float*       out   = (float*)d_out;

    void *pU, *pI, *pDU, *pDI, *pWb;
    cudaGetSymbolAddress(&pU,  g_U);
    cudaGetSymbolAddress(&pI,  g_I);
    cudaGetSymbolAddress(&pDU, g_degU);
    cudaGetSymbolAddress(&pDI, g_degI);
    cudaGetSymbolAddress(&pWb, g_Wb);

    cudaFuncSetAttribute(update_mma_kernel, cudaFuncAttributeMaxDynamicSharedMemorySize, SM_BYTES);

    const size_t embBytes = (size_t)N_USERS * DIM * sizeof(float);
    cudaMemcpyAsync(pU, u_emb, embBytes, cudaMemcpyDeviceToDevice, 0);
    cudaMemcpyAsync(pI, i_emb, embBytes, cudaMemcpyDeviceToDevice, 0);
    cudaMemsetAsync(pDU, 0, sizeof(float) * NUM_R * N_USERS, 0);
    cudaMemsetAsync(pDI, 0, sizeof(float) * NUM_R * N_ITEMS, 0);

    wprep_kernel<<<5, 256>>>(Wp, Ws);
    deg_kernel<<<(NUM_R * N_EDGES + 255) / 256, 256>>>(rows, cols, vals);

    const int spmm_blocks = (N_EDGES * 32 + 255) / 256;
    const __nv_bfloat16* wb = (const __nv_bfloat16*)pWb;

    // g_AGG invariant: zero at entry of every spmm (static zero-init at load; each
    // update kernel re-zeroes exactly the rows it consumed).
    for (int r = 0; r < NUM_R; ++r) {
        const int*   ro  = rows + (size_t)r * N_EDGES;
        const int*   co  = cols + (size_t)r * N_EDGES;
        const float* va  = vals + (size_t)r * N_EDGES;
        const __nv_bfloat16* wp_pair = wb;                                // Wp hi+lo
        const __nv_bfloat16* ws_pair = wb + (size_t)(1 + r) * 2 * 16384;  // Ws[r] hi+lo

        // ---- u update ----
        spmm_kernel<<<spmm_blocks, 256>>>((const float*)pI, co, ro, va);
        update_mma_kernel<<<GRID_U, 256, SM_BYTES>>>(
            (float*)pU, (const float*)pDU + (size_t)r * N_USERS, wp_pair, ws_pair, N_USERS);

        // ---- i update (uses updated U) ----
        spmm_kernel<<<spmm_blocks, 256>>>((const float*)pU, ro, co, va);
        update_mma_kernel<<<GRID_U, 256, SM_BYTES>>>(
            (float*)pI, (const float*)pDI + (size_t)r * N_ITEMS, wp_pair, ws_pair, N_ITEMS);
    }

    const size_t total4 = 2 * ((size_t)N_USERS * DIM / 4);
    finalize_kernel<<<(unsigned)((total4 + 255) / 256), 256>>>(out);
}

// round 7
// speedup vs baseline: 2.0440x; 1.3949x over previous
#include <cuda_runtime.h>
#include <cuda_bf16.h>
#include <mma.h>
#include <cstdint>
#include <cstring>

using namespace nvcuda;

#define N_USERS 100000
#define N_ITEMS 100000
#define DIM     128
#define NUM_R   4
#define N_EDGES 1000000

#define GRID_U  148
#define TM      64
#define NT      ((N_USERS + TM - 1) / TM)   // 1563

#define SCAN_N  (2 * NUM_R * N_USERS)       // 800000 count slots (4 R-dir + 4 C-dir)
#define NTILES  ((SCAN_N + 1023) / 1024)    // 782
#define TOT_E   (2 * NUM_R * N_EDGES)       // 8M csr entries

// ---------------- device scratch (static globals; no allocation) ----------------
__device__ float g_U[(size_t)N_USERS * DIM];
__device__ float g_I[(size_t)N_ITEMS * DIM];
__device__ float g_AGG[(size_t)N_USERS * DIM];
__device__ float g_degU[NUM_R * N_USERS];
__device__ float g_degI[NUM_R * N_ITEMS];
__device__ __nv_bfloat16 g_Wb[(size_t)5 * 2 * 16384];   // Wp,Ws[0..3] x hi,lo, [n][k] bf16
__device__ int  g_cnt[SCAN_N];
__device__ int  g_cur[SCAN_N];
__device__ int  g_off[SCAN_N + 1];
__device__ int  g_tile[NTILES];
__device__ int2 g_csr[TOT_E];               // {src, val_bits}, segment (d,r) at (d*4+r)*1M

// ---------------- count + degree (merged) ----------------
__global__ void count_kernel(const int* __restrict__ rows, const int* __restrict__ cols,
                             const float* __restrict__ vals)
{
    int idx = blockIdx.x * blockDim.x + threadIdx.x;
    if (idx >= NUM_R * N_EDGES) return;
    int r = idx / N_EDGES;
    int row = rows[idx], col = cols[idx];
    float v = vals[idx];
    atomicAdd(&g_degU[r * N_USERS + row], v);
    atomicAdd(&g_degI[r * N_ITEMS + col], v);
    atomicAdd(&g_cnt[r * N_USERS + row], 1);
    atomicAdd(&g_cnt[NUM_R * N_USERS + r * N_ITEMS + col], 1);
}

// ---------------- 3-kernel exclusive scan over g_cnt -> g_off ----------------
__global__ __launch_bounds__(256) void scan1_kernel()
{
    __shared__ int ssum[256];
    int t = threadIdx.x;
    int base = blockIdx.x * 1024 + t * 4;
    int c[4];
#pragma unroll
    for (int j = 0; j < 4; ++j) c[j] = (base + j < SCAN_N) ? g_cnt[base + j] : 0;
    int tsum = c[0] + c[1] + c[2] + c[3];
    ssum[t] = tsum;
    __syncthreads();
#pragma unroll
    for (int o = 1; o < 256; o <<= 1) {
        int v = (t >= o) ? ssum[t - o] : 0;
        __syncthreads();
        ssum[t] += v;
        __syncthreads();
    }
    int run = ssum[t] - tsum;   // exclusive within tile
#pragma unroll
    for (int j = 0; j < 4; ++j) {
        if (base + j < SCAN_N) g_off[base + j] = run;
        run += c[j];
    }
    if (t == 255) g_tile[blockIdx.x] = ssum[255];
}

__global__ __launch_bounds__(1024) void scan2_kernel()
{
    __shared__ int s[1024];
    int t = threadIdx.x;
    int orig = (t < NTILES) ? g_tile[t] : 0;
    s[t] = orig;
    __syncthreads();
#pragma unroll
    for (int o = 1; o < 1024; o <<= 1) {
        int v = (t >= o) ? s[t - o] : 0;
        __syncthreads();
        s[t] += v;
        __syncthreads();
    }
    if (t < NTILES) g_tile[t] = s[t] - orig;   // exclusive
}

__global__ __launch_bounds__(256) void scan3_kernel()
{
    int add = g_tile[blockIdx.x];
    int base = blockIdx.x * 1024 + threadIdx.x * 4;
#pragma unroll
    for (int j = 0; j < 4; ++j)
        if (base + j < SCAN_N) g_off[base + j] += add;
    if (blockIdx.x == 0 && threadIdx.x == 0) g_off[SCAN_N] = TOT_E;
}

// ---------------- CSR fill ----------------
__global__ void fill_kernel(const int* __restrict__ rows, const int* __restrict__ cols,
                            const float* __restrict__ vals)
{
    int idx = blockIdx.x * blockDim.x + threadIdx.x;
    if (idx >= NUM_R * N_EDGES) return;
    int r = idx / N_EDGES;
    int row = rows[idx], col = cols[idx];
    int vb = __float_as_int(vals[idx]);
    int kR = r * N_USERS + row;
    int pR = g_off[kR] + atomicAdd(&g_cur[kR], 1);
    g_csr[pR] = make_int2(col, vb);
    int kC = NUM_R * N_USERS + r * N_ITEMS + col;
    int pC = g_off[kC] + atomicAdd(&g_cur[kC], 1);
    g_csr[pC] = make_int2(row, vb);
}

// ---------------- CSR SpMM: warp per dst row, gather + register reduce ----------------
__global__ __launch_bounds__(256) void spmm_csr_kernel(const float* __restrict__ feats,
                                                       int kbase)
{
    int gw = (blockIdx.x * blockDim.x + threadIdx.x) >> 5;
    int lane = threadIdx.x & 31;
    if (gw >= N_USERS) return;
    int e0 = g_off[kbase + gw];
    int e1 = g_off[kbase + gw + 1];
    float4 acc0 = make_float4(0.f, 0.f, 0.f, 0.f);
    float4 acc1 = make_float4(0.f, 0.f, 0.f, 0.f);
    int e = e0;
    for (; e + 1 < e1; e += 2) {
        int2 p0 = __ldg(&g_csr[e]);
        int2 p1 = __ldg(&g_csr[e + 1]);
        float v0 = __int_as_float(p0.y), v1 = __int_as_float(p1.y);
        float4 x0 = __ldg(&reinterpret_cast<const float4*>(feats + (size_t)p0.x * DIM)[lane]);
        float4 x1 = __ldg(&reinterpret_cast<const float4*>(feats + (size_t)p1.x * DIM)[lane]);
        acc0.x = fmaf(v0, x0.x, acc0.x); acc0.y = fmaf(v0, x0.y, acc0.y);
        acc0.z = fmaf(v0, x0.z, acc0.z); acc0.w = fmaf(v0, x0.w, acc0.w);
        acc1.x = fmaf(v1, x1.x, acc1.x); acc1.y = fmaf(v1, x1.y, acc1.y);
        acc1.z = fmaf(v1, x1.z, acc1.z); acc1.w = fmaf(v1, x1.w, acc1.w);
    }
    if (e < e1) {
        int2 p = __ldg(&g_csr[e]);
        float v = __int_as_float(p.y);
        float4 x = __ldg(&reinterpret_cast<const float4*>(feats + (size_t)p.x * DIM)[lane]);
        acc0.x = fmaf(v, x.x, acc0.x); acc0.y = fmaf(v, x.y, acc0.y);
        acc0.z = fmaf(v, x.z, acc0.z); acc0.w = fmaf(v, x.w, acc0.w);
    }
    acc0.x += acc1.x; acc0.y += acc1.y; acc0.z += acc1.z; acc0.w += acc1.w;
    reinterpret_cast<float4*>(g_AGG + (size_t)gw * DIM)[lane] = acc0;
}

// ---------------- weight prep: transpose + bf16 split ----------------
__global__ __launch_bounds__(256) void wprep_kernel(const float* __restrict__ Wp,
                                                    const float* __restrict__ Ws)
{
    int w = blockIdx.x;
    const float* W = (w == 0) ? Wp : Ws + (size_t)(w - 1) * DIM * DIM;
    __nv_bfloat16* hi = g_Wb + (size_t)w * 2 * 16384;
    __nv_bfloat16* lo = hi + 16384;
    for (int e = threadIdx.x; e < DIM * DIM; e += blockDim.x) {
        int k = e >> 7, n = e & 127;
        float x = W[e];
        __nv_bfloat16 h = __float2bfloat16(x);
        __nv_bfloat16 l = __float2bfloat16(x - __bfloat162float(h));
        hi[n * DIM + k] = h;
        lo[n * DIM + k] = l;
    }
}

// ================= persistent WMMA update GEMM (as round 6, minus AGG zeroing) =====
#define LDA       136
#define ASTRIDE_B (LDA * 2)
#define SM_INV    0
#define SM_STAGE  1024
#define SM_AH     (SM_STAGE + 32768)
#define SM_AL     (SM_AH + TM * ASTRIDE_B)
#define SM_B      (SM_AL + TM * ASTRIDE_B)
#define BMAT      (128 * ASTRIDE_B)
#define SM_BYTES  (SM_B + 4 * BMAT)

typedef wmma::fragment<wmma::matrix_a, 16, 16, 16, __nv_bfloat16, wmma::row_major> FragA;
typedef wmma::fragment<wmma::matrix_b, 16, 16, 16, __nv_bfloat16, wmma::col_major> FragB;
typedef wmma::fragment<wmma::accumulator, 16, 16, 16, float> FragC;

__device__ __forceinline__ uint32_t smem_u32(const void* p) {
    uint32_t a;
    asm("{ .reg .u64 t; cvta.to.shared.u64 t, %1; cvt.u32.u64 %0, t; }" : "=r"(a) : "l"(p));
    return a;
}
__device__ __forceinline__ void cp_async16(uint32_t smem_dst, const void* gsrc) {
    asm volatile("cp.async.cg.shared.global [%0], [%1], 16;" :: "r"(smem_dst), "l"(gsrc));
}
#define CP_COMMIT() asm volatile("cp.async.commit_group;" ::: "memory")
#define CP_WAIT0()  asm volatile("cp.async.wait_group 0;" ::: "memory")

__device__ __forceinline__ void stage_load(const float* __restrict__ src, int bm, int M,
                                           uint32_t stageAddr, int tid)
{
#pragma unroll
    for (int i = 0; i < 8; ++i) {
        int idx = i * 256 + tid;
        int r = idx >> 5, c4 = idx & 31;
        int rowg = bm + r;
        if (rowg >= M) rowg = M - 1;
        cp_async16(stageAddr + (uint32_t)idx * 16, src + (size_t)rowg * DIM + c4 * 4);
    }
    CP_COMMIT();
}

__device__ __forceinline__ void cvt_stage(const char* __restrict__ stage, char* hi, char* lo,
                                          const float* sInv, int tid, bool scale)
{
#pragma unroll
    for (int it = 0; it < 8; ++it) {
        int idx = it * 256 + tid;
        int r = idx >> 5, c4 = idx & 31;
        float4 v = *reinterpret_cast<const float4*>(stage + (size_t)idx * 16);
        if (scale) { float s = sInv[r]; v.x *= s; v.y *= s; v.z *= s; v.w *= s; }
        __nv_bfloat162 h01 = __floats2bfloat162_rn(v.x, v.y);
        __nv_bfloat162 h23 = __floats2bfloat162_rn(v.z, v.w);
        __nv_bfloat162 l01 = __floats2bfloat162_rn(v.x - __bfloat162float(h01.x),
                                                   v.y - __bfloat162float(h01.y));
        __nv_bfloat162 l23 = __floats2bfloat162_rn(v.z - __bfloat162float(h23.x),
                                                   v.w - __bfloat162float(h23.y));
        uint32_t off = (uint32_t)r * ASTRIDE_B + (uint32_t)c4 * 8;
        uint2 hv, lv;
        memcpy(&hv.x, &h01, 4); memcpy(&hv.y, &h23, 4);
        memcpy(&lv.x, &l01, 4); memcpy(&lv.y, &l23, 4);
        *reinterpret_cast<uint2*>(hi + off) = hv;
        *reinterpret_cast<uint2*>(lo + off) = lv;
    }
}

__device__ __forceinline__ void mma_term(const __nv_bfloat16* aStrip,
                                         const __nv_bfloat16* bStrip,
                                         FragC (&acc)[2][2])
{
#pragma unroll
    for (int ks = 0; ks < 8; ++ks) {
        FragA a[2];
        FragB b[2];
#pragma unroll
        for (int mi = 0; mi < 2; ++mi)
            wmma::load_matrix_sync(a[mi], aStrip + (size_t)(mi * 16) * LDA + ks * 16, LDA);
#pragma unroll
        for (int j = 0; j < 2; ++j)
            wmma::load_matrix_sync(b[j], bStrip + (size_t)(j * 16) * LDA + ks * 16, LDA);
#pragma unroll
        for (int mi = 0; mi < 2; ++mi)
#pragma unroll
            for (int j = 0; j < 2; ++j)
                wmma::mma_sync(acc[mi][j], a[mi], b[j], acc[mi][j]);
    }
}

__global__ __launch_bounds__(256, 1)
void update_mma_kernel(float* __restrict__ X, const float* __restrict__ deg,
                       const __nv_bfloat16* __restrict__ wp_pair,
                       const __nv_bfloat16* __restrict__ ws_pair, int M)
{
    extern __shared__ char sm[];
    const uint32_t sb = smem_u32(sm);
    const int tid = threadIdx.x;
    const int wid = tid >> 5;
    const int mg  = wid & 1;
    const int ng  = wid >> 1;

    {
        const float4* srcs[4] = {
            reinterpret_cast<const float4*>(wp_pair),
            reinterpret_cast<const float4*>(wp_pair + 16384),
            reinterpret_cast<const float4*>(ws_pair),
            reinterpret_cast<const float4*>(ws_pair + 16384)};
#pragma unroll
        for (int w = 0; w < 4; ++w) {
            char* dst = sm + SM_B + w * BMAT;
#pragma unroll
            for (int i = 0; i < 8; ++i) {
                int idx = i * 256 + tid;
                int row = idx >> 4, c = idx & 15;
                *reinterpret_cast<float4*>(dst + (uint32_t)row * ASTRIDE_B + c * 16) = srcs[w][idx];
            }
        }
    }

    float* sInv = (float*)(sm + SM_INV);
    const uint32_t stageAddr = sb + SM_STAGE;
    char* stage = sm + SM_STAGE;
    char* aHbuf = sm + SM_AH;
    char* aLbuf = sm + SM_AL;

    const __nv_bfloat16* aH = (const __nv_bfloat16*)aHbuf + (size_t)mg * 32 * LDA;
    const __nv_bfloat16* aL = (const __nv_bfloat16*)aLbuf + (size_t)mg * 32 * LDA;
    const __nv_bfloat16* bPH = (const __nv_bfloat16*)(sm + SM_B + 0 * BMAT) + (size_t)ng * 32 * LDA;
    const __nv_bfloat16* bPL = (const __nv_bfloat16*)(sm + SM_B + 1 * BMAT) + (size_t)ng * 32 * LDA;
    const __nv_bfloat16* bSH = (const __nv_bfloat16*)(sm + SM_B + 2 * BMAT) + (size_t)ng * 32 * LDA;
    const __nv_bfloat16* bSL = (const __nv_bfloat16*)(sm + SM_B + 3 * BMAT) + (size_t)ng * 32 * LDA;

    stage_load(X, (int)blockIdx.x * TM, M, stageAddr, tid);

    for (int t = blockIdx.x; t < NT; t += GRID_U) {
        const int bm = t * TM;
        if (tid < TM) {
            int rowg = bm + tid;
            sInv[tid] = (rowg < M) ? 1.0f / (deg[rowg] + 1.0f) : 0.0f;
        }

        FragC acc[2][2];
#pragma unroll
        for (int mi = 0; mi < 2; ++mi)
#pragma unroll
            for (int j = 0; j < 2; ++j) wmma::fill_fragment(acc[mi][j], 0.0f);

        // phase 0: A = X, B = Wp
        CP_WAIT0();
        __syncthreads();
        cvt_stage(stage, aHbuf, aLbuf, sInv, tid, false);
        __syncthreads();
        stage_load(g_AGG, bm, M, stageAddr, tid);
        mma_term(aH, bPH, acc);
        mma_term(aH, bPL, acc);
        mma_term(aL, bPH, acc);

        // phase 1: A = inv*AGG, B = Ws
        CP_WAIT0();
        __syncthreads();
        cvt_stage(stage, aHbuf, aLbuf, sInv, tid, true);
        __syncthreads();
        if (t + GRID_U < NT)
            stage_load(X, (t + GRID_U) * TM, M, stageAddr, tid);
        mma_term(aH, bSH, acc);
        mma_term(aH, bSL, acc);
        mma_term(aL, bSH, acc);

        // epilogue: direct global store
#pragma unroll
        for (int mi = 0; mi < 2; ++mi) {
            int row0 = bm + mg * 32 + mi * 16;
            if (row0 < M) {
#pragma unroll
                for (int j = 0; j < 2; ++j)
                    wmma::store_matrix_sync(X + (size_t)row0 * DIM + ng * 32 + j * 16,
                                            acc[mi][j], DIM, wmma::mem_row_major);
            }
        }
    }
}

// ---------------- final leaky-relu + write out [U ; I] ----------------
__global__ void finalize_kernel(float* __restrict__ out)
{
    const size_t half4  = (size_t)N_USERS * DIM / 4;
    const size_t total4 = 2 * half4;
    size_t idx = (size_t)blockIdx.x * blockDim.x + threadIdx.x;
    if (idx >= total4) return;
    float4 v = (idx < half4) ? reinterpret_cast<const float4*>(g_U)[idx]
                             : reinterpret_cast<const float4*>(g_I)[idx - half4];
    v.x = v.x > 0.f ? v.x : 0.01f * v.x;
    v.y = v.y > 0.f ? v.y : 0.01f * v.y;
    v.z = v.z > 0.f ? v.z : 0.01f * v.z;
    v.w = v.w > 0.f ? v.w : 0.01f * v.w;
    reinterpret_cast<float4*>(out)[idx] = v;
}

// ---------------- launch ----------------
extern "C" void kernel_launch(void* const* d_in, const int* in_sizes, int n_in,
                              void* d_out, int out_size)
{
    const float* u_emb = (const float*)d_in[0];
    const float* i_emb = (const float*)d_in[1];
    const float* Wp    = (const float*)d_in[2];
    const float* Ws    = (const float*)d_in[3];
    const float* vals  = (const float*)d_in[4];
    const int*   rows  = (const int*)d_in[5];
    const int*   cols  = (const int*)d_in[6];
    float*       out   = (float*)d_out;

    void *pU, *pI, *pDU, *pDI, *pWb, *pCnt, *pCur;
    cudaGetSymbolAddress(&pU,  g_U);
    cudaGetSymbolAddress(&pI,  g_I);
    cudaGetSymbolAddress(&pDU, g_degU);
    cudaGetSymbolAddress(&pDI, g_degI);
    cudaGetSymbolAddress(&pWb, g_Wb);
    cudaGetSymbolAddress(&pCnt, g_cnt);
    cudaGetSymbolAddress(&pCur, g_cur);

    cudaFuncSetAttribute(update_mma_kernel, cudaFuncAttributeMaxDynamicSharedMemorySize, SM_BYTES);

    const size_t embBytes = (size_t)N_USERS * DIM * sizeof(float);
    cudaMemcpyAsync(pU, u_emb, embBytes, cudaMemcpyDeviceToDevice, 0);
    cudaMemcpyAsync(pI, i_emb, embBytes, cudaMemcpyDeviceToDevice, 0);
    cudaMemsetAsync(pDU, 0, sizeof(float) * NUM_R * N_USERS, 0);
    cudaMemsetAsync(pDI, 0, sizeof(float) * NUM_R * N_ITEMS, 0);
    cudaMemsetAsync(pCnt, 0, sizeof(int) * SCAN_N, 0);
    cudaMemsetAsync(pCur, 0, sizeof(int) * SCAN_N, 0);

    wprep_kernel<<<5, 256>>>(Wp, Ws);
    count_kernel<<<(NUM_R * N_EDGES + 255) / 256, 256>>>(rows, cols, vals);
    scan1_kernel<<<NTILES, 256>>>();
    scan2_kernel<<<1, 1024>>>();
    scan3_kernel<<<NTILES, 256>>>();
    fill_kernel<<<(NUM_R * N_EDGES + 255) / 256, 256>>>(rows, cols, vals);

    const int spmm_blocks = (N_USERS * 32 + 255) / 256;  // warp per dst row
    const __nv_bfloat16* wb = (const __nv_bfloat16*)pWb;

    for (int r = 0; r < NUM_R; ++r) {
        const __nv_bfloat16* wp_pair = wb;
        const __nv_bfloat16* ws_pair = wb + (size_t)(1 + r) * 2 * 16384;

        // ---- u update: CSR segment r (dst = rows, src = cols), feats = I ----
        spmm_csr_kernel<<<spmm_blocks, 256>>>((const float*)pI, r * N_USERS);
        update_mma_kernel<<<GRID_U, 256, SM_BYTES>>>(
            (float*)pU, (const float*)pDU + (size_t)r * N_USERS, wp_pair, ws_pair, N_USERS);

        // ---- i update: CSR segment NUM_R + r (dst = cols, src = rows), feats = U ----
        spmm_csr_kernel<<<spmm_blocks, 256>>>((const float*)pU, (NUM_R + r) * N_ITEMS);
        update_mma_kernel<<<GRID_U, 256, SM_BYTES>>>(
            (float*)pI, (const float*)pDI + (size_t)r * N_ITEMS, wp_pair, ws_pair, N_ITEMS);
    }

    const size_t total4 = 2 * ((size_t)N_USERS * DIM / 4);
    finalize_kernel<<<(unsigned)((total4 + 255) / 256), 256>>>(out);
}